// round 11
// baseline (speedup 1.0000x reference)
#include <cuda_runtime.h>
#include <cstdint>

#define BATCH 16
#define NV    20000
#define FIN   64
#define COUT  64
#define KNB   16

#define GEMM_BLKS   157      // ceil(20000/128)
#define GATHER_BLKS 625      // 20000/32
#define STAGE_BLKS  (GEMM_BLKS + GATHER_BLKS)

// Scratch: y = x @ Wn with a zero pad row at index 0.  [B][V+1][COUT]
__device__ float g_y[(size_t)BATCH * (NV + 1) * COUT];
// Weights in mma-fragment order: [mat(2)][ks(8)][nt(8)][lane(32)][2] tf32 bits
__device__ uint32_t g_wfrag[2 * 8 * 8 * 32 * 2];

// ---------------------------------------------------------------------------
// Pre-kernel: swizzle Wx/Wn into m16n8k8 B-fragment order (tf32),
// and zero the pad rows of g_y (row 0 of each batch).
// ---------------------------------------------------------------------------
__global__ void wfrag_build_kernel(const float* __restrict__ Wx,
                                   const float* __restrict__ Wn)
{
    int i = blockIdx.x * 256 + threadIdx.x;        // 0..16383
    int j    =  i        & 1;
    int lane = (i >> 1)  & 31;
    int nt   = (i >> 6)  & 7;
    int ks   = (i >> 9)  & 7;
    int mat  =  i >> 12;
    int k = (lane & 3) + 4 * j + 8 * ks;
    int n = (lane >> 2) + 8 * nt;
    const float* W = mat ? Wn : Wx;
    float v = W[k * COUT + n];
    uint32_t tv;
    asm("cvt.rna.tf32.f32 %0, %1;" : "=r"(tv) : "f"(v));
    g_wfrag[i] = tv;

    // Zero pad rows: 16 batches * 64 channels = 1024 floats
    if (i < BATCH * COUT) {
        int b = i >> 6;
        int c = i & 63;
        g_y[(size_t)b * (NV + 1) * COUT + c] = 0.f;
    }
}

// ---------------------------------------------------------------------------
// Stage kernel, launch j of 0..16:
//   blocks [0,157)    : GEMM for batch j        (skipped when j == 16)
//   blocks [157,782)  : gather for batch j - 1  (skipped when j == 0)
// GEMM CTAs are tensor/DRAM-bound; gather CTAs are L1/L2-bound -> they
// co-reside on SMs and overlap, hiding one phase under the other.
// ---------------------------------------------------------------------------
__global__ __launch_bounds__(256)
void stage_kernel(const float* __restrict__ x,
                  const float* __restrict__ bias,
                  const int*   __restrict__ neighbor,
                  float*       __restrict__ out,
                  const int    jb)
{
    __shared__ uint32_t sW[2 * 8 * 8 * 32 * 2];    // 32 KB (GEMM role)
    __shared__ int      sN[512];                   // 2 KB  (gather role)

    const int tid = threadIdx.x;

    if (blockIdx.x < GEMM_BLKS) {
        // ================= GEMM role: batch jb ==============================
        if (jb >= BATCH) return;
        const int b = jb;

        // Stage fragment-ordered weights: 2048 uint4, coalesced.
        {
            const uint4* src = (const uint4*)g_wfrag;
            uint4*       dst = (uint4*)sW;
            #pragma unroll
            for (int i = 0; i < 8; ++i)
                dst[tid + i * 256] = src[tid + i * 256];
        }
        __syncthreads();

        const int lane = tid & 31;
        const int wid  = tid >> 5;
        const int g    = lane >> 2;
        const int t    = lane & 3;
        const int vb   = blockIdx.x * 128 + wid * 16;
        const int r0   = vb + g;
        const int r1   = r0 + 8;

        const float* __restrict__ xb = x + (size_t)b * NV * FIN;

        // Prefetch A: 2 rows x 16 cols. 32 independent LDG.32.
        float f0[16], f1[16];
        #pragma unroll
        for (int j = 0; j < 16; ++j) {
            int c = t + 4 * j;
            f0[j] = (r0 < NV) ? __ldg(&xb[(size_t)r0 * FIN + c]) : 0.f;
            f1[j] = (r1 < NV) ? __ldg(&xb[(size_t)r1 * FIN + c]) : 0.f;
        }
        uint32_t ar0[16], ar1[16];
        #pragma unroll
        for (int j = 0; j < 16; ++j) {
            asm("cvt.rna.tf32.f32 %0, %1;" : "=r"(ar0[j]) : "f"(f0[j]));
            asm("cvt.rna.tf32.f32 %0, %1;" : "=r"(ar1[j]) : "f"(f1[j]));
        }

        float accX[8][4] = {{0.f}};
        float accN[8][4] = {{0.f}};

        #pragma unroll
        for (int ks = 0; ks < 8; ++ks) {
            const uint32_t a0 = ar0[2 * ks];
            const uint32_t a1 = ar1[2 * ks];
            const uint32_t a2 = ar0[2 * ks + 1];
            const uint32_t a3 = ar1[2 * ks + 1];

            #pragma unroll
            for (int nt = 0; nt < 8; ++nt) {
                const uint2 bx = *(const uint2*)&sW[((0 * 8 + ks) * 8 + nt) * 64 + lane * 2];
                const uint2 bn = *(const uint2*)&sW[((1 * 8 + ks) * 8 + nt) * 64 + lane * 2];

                asm volatile(
                    "mma.sync.aligned.m16n8k8.row.col.f32.tf32.tf32.f32 "
                    "{%0,%1,%2,%3}, {%4,%5,%6,%7}, {%8,%9}, {%0,%1,%2,%3};"
                    : "+f"(accX[nt][0]), "+f"(accX[nt][1]),
                      "+f"(accX[nt][2]), "+f"(accX[nt][3])
                    : "r"(a0), "r"(a1), "r"(a2), "r"(a3),
                      "r"(bx.x), "r"(bx.y));
                asm volatile(
                    "mma.sync.aligned.m16n8k8.row.col.f32.tf32.tf32.f32 "
                    "{%0,%1,%2,%3}, {%4,%5,%6,%7}, {%8,%9}, {%0,%1,%2,%3};"
                    : "+f"(accN[nt][0]), "+f"(accN[nt][1]),
                      "+f"(accN[nt][2]), "+f"(accN[nt][3])
                    : "r"(a0), "r"(a1), "r"(a2), "r"(a3),
                      "r"(bn.x), "r"(bn.y));
            }
        }

        float* __restrict__ outb = out + (size_t)b * NV * COUT;
        float* __restrict__ yb   = g_y + (size_t)b * (NV + 1) * COUT;
        #pragma unroll
        for (int nt = 0; nt < 8; ++nt) {
            const int c = nt * 8 + 2 * t;
            const float2 bv = *(const float2*)&bias[c];
            if (r0 < NV) {
                *(float2*)&outb[(size_t)r0 * COUT + c] =
                    make_float2(accX[nt][0] + bv.x, accX[nt][1] + bv.y);
                *(float2*)&yb[(size_t)(r0 + 1) * COUT + c] =
                    make_float2(accN[nt][0], accN[nt][1]);
            }
            if (r1 < NV) {
                *(float2*)&outb[(size_t)r1 * COUT + c] =
                    make_float2(accX[nt][2] + bv.x, accX[nt][3] + bv.y);
                *(float2*)&yb[(size_t)(r1 + 1) * COUT + c] =
                    make_float2(accN[nt][2], accN[nt][3]);
            }
        }
    } else {
        // ================= Gather role: batch jb - 1 ========================
        if (jb == 0) return;
        const int b    = jb - 1;
        const int blk  = blockIdx.x - GEMM_BLKS;
        const int warp = tid >> 5;
        const int lane = tid & 31;
        const int half = lane >> 4;          // 0 = even-k rows, 1 = odd-k rows
        const int l16  = lane & 15;
        const int vblk = blk * 32;           // 625 * 32 = 20000 exactly
        const int v0   = vblk + warp * 4;

        // Stage this CTA's 512 neighbor ids (one coalesced 2KB read).
        ((int2*)sN)[tid] = __ldg((const int2*)&neighbor[vblk * KNB] + tid);
        __syncthreads();

        const float* __restrict__ yb = g_y + (size_t)b * (NV + 1) * COUT;

        float4 acc0 = make_float4(0.f, 0.f, 0.f, 0.f);
        float4 acc1 = acc0, acc2 = acc0, acc3 = acc0;

        const int2* ids = (const int2*)&sN[warp * 4 * KNB];

        #pragma unroll
        for (int p = 0; p < 8; ++p) {
            const int2 i0 = ids[0 * 8 + p];          // uniform LDS.64 broadcast
            const int2 i1 = ids[1 * 8 + p];
            const int2 i2 = ids[2 * 8 + p];
            const int2 i3 = ids[3 * 8 + p];
            const int r0 = half ? i0.y : i0.x;       // id; 0 = zero pad row
            const int r1 = half ? i1.y : i1.x;
            const int r2 = half ? i2.y : i2.x;
            const int r3 = half ? i3.y : i3.x;

            const float4 t0 = *(const float4*)(yb + (size_t)r0 * COUT + l16 * 4);
            const float4 t1 = *(const float4*)(yb + (size_t)r1 * COUT + l16 * 4);
            const float4 t2 = *(const float4*)(yb + (size_t)r2 * COUT + l16 * 4);
            const float4 t3 = *(const float4*)(yb + (size_t)r3 * COUT + l16 * 4);

            acc0.x += t0.x; acc0.y += t0.y; acc0.z += t0.z; acc0.w += t0.w;
            acc1.x += t1.x; acc1.y += t1.y; acc1.z += t1.z; acc1.w += t1.w;
            acc2.x += t2.x; acc2.y += t2.y; acc2.z += t2.z; acc2.w += t2.w;
            acc3.x += t3.x; acc3.y += t3.y; acc3.z += t3.z; acc3.w += t3.w;
        }

        // Combine even/odd halves: butterfly across lane 16.
        #pragma unroll
        for (int c = 0; c < 4; ++c) {
            ((float*)&acc0)[c] += __shfl_xor_sync(0xffffffffu, ((float*)&acc0)[c], 16);
            ((float*)&acc1)[c] += __shfl_xor_sync(0xffffffffu, ((float*)&acc1)[c], 16);
            ((float*)&acc2)[c] += __shfl_xor_sync(0xffffffffu, ((float*)&acc2)[c], 16);
            ((float*)&acc3)[c] += __shfl_xor_sync(0xffffffffu, ((float*)&acc3)[c], 16);
        }

        // Pairwise RMW: low half -> v0+0 / v0+2, high half -> v0+1 / v0+3.
        const float s = 1.0f / (float)KNB;
        const float4 sAB = half ? acc1 : acc0;
        const float4 sCD = half ? acc3 : acc2;

        float* opAB = out + ((size_t)b * NV + v0 + half)     * COUT + l16 * 4;
        float* opCD = out + ((size_t)b * NV + v0 + 2 + half) * COUT + l16 * 4;

        float4 oAB = *(const float4*)opAB;
        float4 oCD = *(const float4*)opCD;
        oAB.x += sAB.x * s; oAB.y += sAB.y * s; oAB.z += sAB.z * s; oAB.w += sAB.w * s;
        oCD.x += sCD.x * s; oCD.y += sCD.y * s; oCD.z += sCD.z * s; oCD.w += sCD.w * s;
        *(float4*)opAB = oAB;
        *(float4*)opCD = oCD;
    }
}

extern "C" void kernel_launch(void* const* d_in, const int* in_sizes, int n_in,
                              void* d_out, int out_size)
{
    // metadata order: x, Wx, Wn, b, neighbor
    const float* x        = (const float*)d_in[0];
    const float* Wx       = (const float*)d_in[1];
    const float* Wn       = (const float*)d_in[2];
    const float* bias     = (const float*)d_in[3];
    const int*   neighbor = (const int*)d_in[4];
    float*       out      = (float*)d_out;

    wfrag_build_kernel<<<64, 256>>>(Wx, Wn);

    // Pipeline: launch j runs GEMM(batch j) concurrently with gather(batch j-1).
    for (int j = 0; j <= BATCH; ++j)
        stage_kernel<<<STAGE_BLKS, 256>>>(x, bias, neighbor, out, j);
}